// round 2
// baseline (speedup 1.0000x reference)
#include <cuda_runtime.h>

#define NN 100000
#define NE 1600000
#define NG 128

// ---- scratch (device globals; no allocation allowed) ----
__device__ float d_deg[NN];
__device__ float d_dinv[NN];
__device__ float d_g1[NN * 64];     // dinv[i] * (x@W1)[i]
__device__ float d_acc1[NN * 64];   // conv1 accumulator
__device__ float d_g2[NN * 128];    // dinv[i] * (h1@W2)[i]
__device__ float d_acc2[NN * 128];  // conv2 accumulator
__device__ float d_cnt[NG];
__device__ int   d_idx64;           // 1 if indices are int64, 0 if int32

// ---- runtime index-width probe ----
// If the data is really int32, an int64 view combines two random values in
// [0,1e5): the high half is nonzero w.p. ~(1-1e-5), so value >= 2^32.
__global__ void k_probe(const void* __restrict__ ei) {
    if (threadIdx.x == 0 && blockIdx.x == 0) {
        const long long* p = (const long long*)ei;
        int ok = 1;
        for (int i = 0; i < 16; i++) {
            long long v = p[i];
            if (v < 0 || v >= NN) ok = 0;
        }
        d_idx64 = ok;
    }
}

__device__ __forceinline__ int load_idx(const void* p, long long i) {
    if (d_idx64) return (int)((const long long*)p)[i];
    return ((const int*)p)[i];
}

// ---- K1: deg = 1 (self loop) ----
__global__ void k_init_deg() {
    int i = blockIdx.x * blockDim.x + threadIdx.x;
    if (i < NN) d_deg[i] = 1.0f;
}

// ---- K2: in-degree count ----
__global__ void k_deg(const void* __restrict__ ei) {
    int e = blockIdx.x * blockDim.x + threadIdx.x;
    if (e < NE) {
        int dst = load_idx(ei, (long long)NE + e);
        atomicAdd(&d_deg[dst], 1.0f);
    }
}

// ---- K3: dinv, g1 = dinv*(x@W1), acc1 = dinv*g1 (self-loop term) ----
// 256 threads = 4 nodes x 64 cols
__global__ void k_node1(const float* __restrict__ x, const float* __restrict__ W1) {
    __shared__ float sW[192];
    int tid = threadIdx.x;
    if (tid < 192) sW[tid] = W1[tid];
    __syncthreads();
    int node = blockIdx.x * 4 + (tid >> 6);
    int c = tid & 63;
    float x0 = x[node * 3], x1 = x[node * 3 + 1], x2 = x[node * 3 + 2];
    float h = fmaf(x0, sW[c], fmaf(x1, sW[64 + c], x2 * sW[128 + c]));
    float di = rsqrtf(d_deg[node]);
    if (c == 0) d_dinv[node] = di;
    float g = di * h;
    d_g1[(size_t)node * 64 + c] = g;
    d_acc1[(size_t)node * 64 + c] = di * g;
}

// ---- K4: edge scatter, 64 feats. 16 threads/edge, one float4 each ----
__global__ void k_edge64(const void* __restrict__ ei) {
    long long t = (long long)blockIdx.x * blockDim.x + threadIdx.x;
    int e = (int)(t >> 4);
    int q = (int)(t & 15);
    if (e >= NE) return;
    int src = load_idx(ei, e);
    int dst = load_idx(ei, (long long)NE + e);
    float nd = d_dinv[dst];
    const float4* gp = (const float4*)(d_g1 + (size_t)src * 64);
    float4 v = gp[q];
    float* ap = d_acc1 + (size_t)dst * 64 + q * 4;
    asm volatile("red.global.add.v4.f32 [%0], {%1,%2,%3,%4};"
                 :: "l"(ap), "f"(v.x * nd), "f"(v.y * nd), "f"(v.z * nd), "f"(v.w * nd)
                 : "memory");
}

// ---- K5: h1=relu(acc1+b1); h2lin=h1@W2; g2=dinv*h2lin; acc2=dinv*g2 ----
// 256 threads: 8 warps, one node per warp; W2 (64x128) staged in shared.
__global__ void k_node2(const float* __restrict__ W2, const float* __restrict__ b1) {
    __shared__ float sW[64 * 128];
    __shared__ float sh[8][64];
    int tid = threadIdx.x;
    for (int i = tid; i < 8192; i += 256) sW[i] = W2[i];
    int warp = tid >> 5, lane = tid & 31;
    int node = blockIdx.x * 8 + warp;
    float a0 = fmaxf(d_acc1[(size_t)node * 64 + lane] + b1[lane], 0.0f);
    float a1 = fmaxf(d_acc1[(size_t)node * 64 + 32 + lane] + b1[32 + lane], 0.0f);
    sh[warp][lane] = a0;
    sh[warp][32 + lane] = a1;
    __syncthreads();
    float o0 = 0.f, o1 = 0.f, o2 = 0.f, o3 = 0.f;
#pragma unroll
    for (int k = 0; k < 64; k++) {
        float hk = sh[warp][k];
        const float* w = sW + k * 128 + lane;
        o0 = fmaf(hk, w[0],  o0);
        o1 = fmaf(hk, w[32], o1);
        o2 = fmaf(hk, w[64], o2);
        o3 = fmaf(hk, w[96], o3);
    }
    float di = d_dinv[node];
    size_t b = (size_t)node * 128 + lane;
    d_g2[b]        = di * o0;
    d_g2[b + 32]   = di * o1;
    d_g2[b + 64]   = di * o2;
    d_g2[b + 96]   = di * o3;
    float d2 = di * di;
    d_acc2[b]      = d2 * o0;
    d_acc2[b + 32] = d2 * o1;
    d_acc2[b + 64] = d2 * o2;
    d_acc2[b + 96] = d2 * o3;
}

// ---- K6: edge scatter, 128 feats. 32 threads/edge (1 warp), one float4 each ----
__global__ void k_edge128(const void* __restrict__ ei) {
    long long t = (long long)blockIdx.x * blockDim.x + threadIdx.x;
    int e = (int)(t >> 5);
    int q = (int)(t & 31);
    if (e >= NE) return;
    int src = load_idx(ei, e);
    int dst = load_idx(ei, (long long)NE + e);
    float nd = d_dinv[dst];
    const float4* gp = (const float4*)(d_g2 + (size_t)src * 128);
    float4 v = gp[q];
    float* ap = d_acc2 + (size_t)dst * 128 + q * 4;
    asm volatile("red.global.add.v4.f32 [%0], {%1,%2,%3,%4};"
                 :: "l"(ap), "f"(v.x * nd), "f"(v.y * nd), "f"(v.z * nd), "f"(v.w * nd)
                 : "memory");
}

// ---- K7a: zero output + counts ----
__global__ void k_zero(float* __restrict__ out) {
    int i = blockIdx.x * blockDim.x + threadIdx.x;
    if (i < NG * NG) out[i] = 0.0f;
    if (i < NG) d_cnt[i] = 0.0f;
}

// ---- K7b: per-graph node counts ----
__global__ void k_cnt(const void* __restrict__ batch) {
    int i = blockIdx.x * blockDim.x + threadIdx.x;
    if (i < NN) {
        int g = load_idx(batch, i);
        atomicAdd(&d_cnt[g], 1.0f);
    }
}

// ---- K7c: pooling sum. batch is sorted: block handles 32 consecutive nodes,
// thread = feature column; flush accumulator on graph change. ----
__global__ void k_pool(const void* __restrict__ batch, float* __restrict__ out) {
    int c = threadIdx.x;            // 0..127
    int n0 = blockIdx.x * 32;
    int cur = load_idx(batch, n0);
    float s = 0.0f;
    for (int j = 0; j < 32; j++) {
        int i = n0 + j;
        int g = load_idx(batch, i);
        if (g != cur) {
            atomicAdd(&out[cur * 128 + c], s);
            s = 0.0f;
            cur = g;
        }
        s += d_acc2[(size_t)i * 128 + c];
    }
    atomicAdd(&out[cur * 128 + c], s);
}

// ---- K7d: divide by counts, add b2 (pool of (h2+b2) == mean(h2)+b2) ----
__global__ void k_final(float* __restrict__ out, const float* __restrict__ b2) {
    int i = blockIdx.x * blockDim.x + threadIdx.x;
    if (i < NG * NG) {
        int g = i >> 7, c = i & 127;
        out[i] = out[i] / fmaxf(d_cnt[g], 1.0f) + b2[c];
    }
}

extern "C" void kernel_launch(void* const* d_in, const int* in_sizes, int n_in,
                              void* d_out, int out_size) {
    const float* x     = (const float*)d_in[0];
    const void*  ei    = d_in[1];             // int64 or int32, probed at runtime
    const void*  batch = d_in[2];
    const float* W1    = (const float*)d_in[3];
    const float* b1    = (const float*)d_in[4];
    const float* W2    = (const float*)d_in[5];
    const float* b2    = (const float*)d_in[6];
    float* out = (float*)d_out;

    k_probe<<<1, 32>>>(ei);
    k_init_deg<<<(NN + 255) / 256, 256>>>();
    k_deg<<<(NE + 255) / 256, 256>>>(ei);
    k_node1<<<NN / 4, 256>>>(x, W1);
    k_edge64<<<(NE * 16) / 256, 256>>>(ei);
    k_node2<<<NN / 8, 256>>>(W2, b1);
    k_edge128<<<((long long)NE * 32) / 256, 256>>>(ei);
    k_zero<<<(NG * NG + 255) / 256, 256>>>(out);
    k_cnt<<<(NN + 255) / 256, 256>>>(batch);
    k_pool<<<NN / 32, 128>>>(batch, out);
    k_final<<<(NG * NG + 255) / 256, 256>>>(out, b2);
}

// round 3
// speedup vs baseline: 1.4524x; 1.4524x over previous
#include <cuda_runtime.h>

#define NN 100000
#define NE 1600000
#define NG 128
#define SCAN_B 256
#define NBLK ((NN + SCAN_B - 1) / SCAN_B)   // 391

// ---- scratch (device globals; no allocation allowed) ----
__device__ int   d_indeg[NN];
__device__ int   d_off[NN];
__device__ int   d_cur[NN];
__device__ int   d_bsum[NBLK];
__device__ int   d_csr[NE];          // src indices bucketed by dst
__device__ float d_dinv[NN];
__device__ float d_g1[NN * 64];      // dinv[i] * (x@W1)[i]
__device__ float d_h1[NN * 64];      // relu(conv1)
__device__ float d_g2[NN * 128];     // dinv[i] * (h1@W2)[i]
__device__ float d_h2[NN * 128];     // conv2 (without b2)
__device__ float d_cnt[NG];
__device__ int   d_idx64;

// ---- runtime index-width probe (int64 vs silently-int32 JAX indices) ----
__global__ void k_probe(const void* __restrict__ ei) {
    if (threadIdx.x == 0 && blockIdx.x == 0) {
        const long long* p = (const long long*)ei;
        int ok = 1;
        for (int i = 0; i < 16; i++) {
            long long v = p[i];
            if (v < 0 || v >= NN) ok = 0;
        }
        d_idx64 = ok;
    }
}

__device__ __forceinline__ int load_idx(const void* p, long long i) {
    if (d_idx64) return (int)((const long long*)p)[i];
    return ((const int*)p)[i];
}

// ---- zero: indeg, graph counts, output ----
__global__ void k_zero(float* __restrict__ out) {
    int i = blockIdx.x * blockDim.x + threadIdx.x;
    if (i < NN) d_indeg[i] = 0;
    if (i < NG * NG) out[i] = 0.0f;
    if (i < NG) d_cnt[i] = 0.0f;
}

// ---- in-degree count (int atomics) ----
__global__ void k_count(const void* __restrict__ ei) {
    int e = blockIdx.x * blockDim.x + threadIdx.x;
    if (e < NE) {
        int dst = load_idx(ei, (long long)NE + e);
        atomicAdd(&d_indeg[dst], 1);
    }
}

// ---- scan step 1: per-block exclusive scan of indeg ----
__global__ void k_scan1() {
    __shared__ int warp_sums[8];
    int i = blockIdx.x * SCAN_B + threadIdx.x;
    int v = (i < NN) ? d_indeg[i] : 0;
    int lane = threadIdx.x & 31, w = threadIdx.x >> 5;
    int incl = v;
#pragma unroll
    for (int d = 1; d < 32; d <<= 1) {
        int n = __shfl_up_sync(0xffffffffu, incl, d);
        if (lane >= d) incl += n;
    }
    if (lane == 31) warp_sums[w] = incl;
    __syncthreads();
    if (threadIdx.x < 8) {
        int s = warp_sums[threadIdx.x];
#pragma unroll
        for (int d = 1; d < 8; d <<= 1) {
            int n = __shfl_up_sync(0x000000ffu, s, d);
            if ((int)threadIdx.x >= d) s += n;
        }
        warp_sums[threadIdx.x] = s;
    }
    __syncthreads();
    int base = (w > 0) ? warp_sums[w - 1] : 0;
    if (i < NN) d_off[i] = base + incl - v;
    if (threadIdx.x == SCAN_B - 1) d_bsum[blockIdx.x] = base + incl;
}

// ---- scan step 2: exclusive scan of 391 block sums (single block) ----
__global__ void k_scan2() {
    __shared__ int sm[512];
    int t = threadIdx.x;
    int v = (t < NBLK) ? d_bsum[t] : 0;
    sm[t] = v;
    __syncthreads();
    for (int d = 1; d < 512; d <<= 1) {
        int add = (t >= d) ? sm[t - d] : 0;
        __syncthreads();
        sm[t] += add;
        __syncthreads();
    }
    if (t < NBLK) d_bsum[t] = sm[t] - v;
}

// ---- scan step 3: add block offsets; init cursors ----
__global__ void k_scan3() {
    int i = blockIdx.x * blockDim.x + threadIdx.x;
    if (i < NN) {
        int o = d_off[i] + d_bsum[i / SCAN_B];
        d_off[i] = o;
        d_cur[i] = o;
    }
}

// ---- fill CSR buckets ----
__global__ void k_fill(const void* __restrict__ ei) {
    int e = blockIdx.x * blockDim.x + threadIdx.x;
    if (e < NE) {
        int src = load_idx(ei, e);
        int dst = load_idx(ei, (long long)NE + e);
        int pos = atomicAdd(&d_cur[dst], 1);
        d_csr[pos] = src;
    }
}

// ---- dinv, g1 = dinv*(x@W1). 256 threads = 4 nodes x 64 cols ----
__global__ void k_node1(const float* __restrict__ x, const float* __restrict__ W1) {
    __shared__ float sW[192];
    int tid = threadIdx.x;
    if (tid < 192) sW[tid] = W1[tid];
    __syncthreads();
    int node = blockIdx.x * 4 + (tid >> 6);
    int c = tid & 63;
    float x0 = x[node * 3], x1 = x[node * 3 + 1], x2 = x[node * 3 + 2];
    float h = fmaf(x0, sW[c], fmaf(x1, sW[64 + c], x2 * sW[128 + c]));
    float di = rsqrtf((float)d_indeg[node] + 1.0f);   // +1 self loop
    if (c == 0) d_dinv[node] = di;
    d_g1[(size_t)node * 64 + c] = di * h;
}

// ---- aggregation layer 1: warp per node, float2 per lane ----
__global__ void k_agg64(const float* __restrict__ b1) {
    int gw = (blockIdx.x * blockDim.x + threadIdx.x) >> 5;
    int lane = threadIdx.x & 31;
    if (gw >= NN) return;
    int base = d_off[gw];
    int cnt = d_indeg[gw];
    const float2* G = (const float2*)d_g1;
    float2 acc = G[(size_t)gw * 32 + lane];   // self-loop term
    for (int j = 0; j < cnt; j += 32) {
        int idx = j + lane;
        int s = (idx < cnt) ? d_csr[base + idx] : 0;
        int lim = min(32, cnt - j);
#pragma unroll 4
        for (int k = 0; k < lim; k++) {
            int sk = __shfl_sync(0xffffffffu, s, k);
            float2 v = G[(size_t)sk * 32 + lane];
            acc.x += v.x;
            acc.y += v.y;
        }
    }
    float di = d_dinv[gw];
    float o0 = fmaxf(fmaf(di, acc.x, b1[2 * lane]), 0.0f);
    float o1 = fmaxf(fmaf(di, acc.y, b1[2 * lane + 1]), 0.0f);
    ((float2*)d_h1)[(size_t)gw * 32 + lane] = make_float2(o0, o1);
}

// ---- g2 = dinv*(h1@W2). 8 warps, one node per warp; W2 in shared ----
__global__ void k_node2(const float* __restrict__ W2) {
    __shared__ float sW[64 * 128];
    __shared__ float sh[8][64];
    int tid = threadIdx.x;
    for (int i = tid; i < 8192; i += 256) sW[i] = W2[i];
    int warp = tid >> 5, lane = tid & 31;
    int node = blockIdx.x * 8 + warp;
    sh[warp][lane]      = d_h1[(size_t)node * 64 + lane];
    sh[warp][lane + 32] = d_h1[(size_t)node * 64 + 32 + lane];
    __syncthreads();
    float o0 = 0.f, o1 = 0.f, o2 = 0.f, o3 = 0.f;
#pragma unroll
    for (int k = 0; k < 64; k++) {
        float hk = sh[warp][k];
        const float* w = sW + k * 128 + lane;
        o0 = fmaf(hk, w[0],  o0);
        o1 = fmaf(hk, w[32], o1);
        o2 = fmaf(hk, w[64], o2);
        o3 = fmaf(hk, w[96], o3);
    }
    float di = d_dinv[node];
    size_t b = (size_t)node * 128 + lane;
    d_g2[b]      = di * o0;
    d_g2[b + 32] = di * o1;
    d_g2[b + 64] = di * o2;
    d_g2[b + 96] = di * o3;
}

// ---- aggregation layer 2: warp per node, float4 per lane ----
__global__ void k_agg128() {
    int gw = (blockIdx.x * blockDim.x + threadIdx.x) >> 5;
    int lane = threadIdx.x & 31;
    if (gw >= NN) return;
    int base = d_off[gw];
    int cnt = d_indeg[gw];
    const float4* G = (const float4*)d_g2;
    float4 acc = G[(size_t)gw * 32 + lane];   // self-loop term
    for (int j = 0; j < cnt; j += 32) {
        int idx = j + lane;
        int s = (idx < cnt) ? d_csr[base + idx] : 0;
        int lim = min(32, cnt - j);
#pragma unroll 4
        for (int k = 0; k < lim; k++) {
            int sk = __shfl_sync(0xffffffffu, s, k);
            float4 v = G[(size_t)sk * 32 + lane];
            acc.x += v.x;
            acc.y += v.y;
            acc.z += v.z;
            acc.w += v.w;
        }
    }
    float di = d_dinv[gw];
    acc.x *= di; acc.y *= di; acc.z *= di; acc.w *= di;
    ((float4*)d_h2)[(size_t)gw * 32 + lane] = acc;
}

// ---- per-graph node counts ----
__global__ void k_cnt(const void* __restrict__ batch) {
    int i = blockIdx.x * blockDim.x + threadIdx.x;
    if (i < NN) {
        int g = load_idx(batch, i);
        atomicAdd(&d_cnt[g], 1.0f);
    }
}

// ---- pooling sum over sorted batch: 32 nodes/block, flush on change ----
__global__ void k_pool(const void* __restrict__ batch, float* __restrict__ out) {
    int c = threadIdx.x;            // 0..127
    int n0 = blockIdx.x * 32;
    int cur = load_idx(batch, n0);
    float s = 0.0f;
    for (int j = 0; j < 32; j++) {
        int i = n0 + j;
        int g = load_idx(batch, i);
        if (g != cur) {
            atomicAdd(&out[cur * 128 + c], s);
            s = 0.0f;
            cur = g;
        }
        s += d_h2[(size_t)i * 128 + c];
    }
    atomicAdd(&out[cur * 128 + c], s);
}

// ---- divide by counts, add b2 ----
__global__ void k_final(float* __restrict__ out, const float* __restrict__ b2) {
    int i = blockIdx.x * blockDim.x + threadIdx.x;
    if (i < NG * NG) {
        int g = i >> 7, c = i & 127;
        out[i] = out[i] / fmaxf(d_cnt[g], 1.0f) + b2[c];
    }
}

extern "C" void kernel_launch(void* const* d_in, const int* in_sizes, int n_in,
                              void* d_out, int out_size) {
    const float* x     = (const float*)d_in[0];
    const void*  ei    = d_in[1];
    const void*  batch = d_in[2];
    const float* W1    = (const float*)d_in[3];
    const float* b1    = (const float*)d_in[4];
    const float* W2    = (const float*)d_in[5];
    const float* b2    = (const float*)d_in[6];
    float* out = (float*)d_out;

    k_probe<<<1, 32>>>(ei);
    k_zero<<<(NN + 255) / 256, 256>>>(out);
    k_count<<<(NE + 255) / 256, 256>>>(ei);
    k_scan1<<<NBLK, SCAN_B>>>();
    k_scan2<<<1, 512>>>();
    k_scan3<<<(NN + 255) / 256, 256>>>();
    k_fill<<<(NE + 255) / 256, 256>>>(ei);
    k_node1<<<NN / 4, 256>>>(x, W1);
    k_agg64<<<(NN * 32 + 255) / 256, 256>>>(b1);
    k_node2<<<NN / 8, 256>>>(W2);
    k_agg128<<<(NN * 32 + 255) / 256, 256>>>();
    k_cnt<<<(NN + 255) / 256, 256>>>(batch);
    k_pool<<<NN / 32, 128>>>(batch, out);
    k_final<<<(NG * NG + 255) / 256, 256>>>(out, b2);
}

// round 4
// speedup vs baseline: 1.4548x; 1.0016x over previous
#include <cuda_runtime.h>

#define NN 100000
#define NE 1600000
#define NG 128
#define SCAN_B 256
#define NBLK ((NN + SCAN_B - 1) / SCAN_B)   // 391

// ---- scratch (device globals; no allocation allowed) ----
__device__ int   d_indeg[NN];
__device__ int   d_off[NN];
__device__ int   d_cur[NN];
__device__ int   d_bsum[NBLK];
__device__ int   d_csr[NE];          // src indices bucketed by dst
__device__ float d_dinv[NN];
__device__ float d_g1[NN * 64];      // dinv[i] * (x@W1)[i]
__device__ float d_h1[NN * 64];      // relu(conv1)
__device__ float d_g2[NN * 128];     // dinv[i] * (h1@W2)[i]
__device__ float d_h2[NN * 128];     // conv2 (without b2)
__device__ float d_cnt[NG];
__device__ int   d_idx64;

// ---- runtime index-width probe (int64 vs silently-int32 JAX indices) ----
__global__ void k_probe(const void* __restrict__ ei) {
    if (threadIdx.x == 0 && blockIdx.x == 0) {
        const long long* p = (const long long*)ei;
        int ok = 1;
        for (int i = 0; i < 16; i++) {
            long long v = p[i];
            if (v < 0 || v >= NN) ok = 0;
        }
        d_idx64 = ok;
    }
}

__device__ __forceinline__ int load_idx(const void* p, long long i) {
    if (d_idx64) return (int)((const long long*)p)[i];
    return ((const int*)p)[i];
}

// ---- zero: indeg, graph counts, output ----
__global__ void k_zero(float* __restrict__ out) {
    int i = blockIdx.x * blockDim.x + threadIdx.x;
    if (i < NN) d_indeg[i] = 0;
    if (i < NG * NG) out[i] = 0.0f;
    if (i < NG) d_cnt[i] = 0.0f;
}

// ---- in-degree count (int atomics) ----
__global__ void k_count(const void* __restrict__ ei) {
    int e = blockIdx.x * blockDim.x + threadIdx.x;
    if (e < NE) {
        int dst = load_idx(ei, (long long)NE + e);
        atomicAdd(&d_indeg[dst], 1);
    }
}

// ---- scan step 1: per-block exclusive scan of indeg ----
__global__ void k_scan1() {
    __shared__ int warp_sums[8];
    int i = blockIdx.x * SCAN_B + threadIdx.x;
    int v = (i < NN) ? d_indeg[i] : 0;
    int lane = threadIdx.x & 31, w = threadIdx.x >> 5;
    int incl = v;
#pragma unroll
    for (int d = 1; d < 32; d <<= 1) {
        int n = __shfl_up_sync(0xffffffffu, incl, d);
        if (lane >= d) incl += n;
    }
    if (lane == 31) warp_sums[w] = incl;
    __syncthreads();
    if (threadIdx.x < 8) {
        int s = warp_sums[threadIdx.x];
#pragma unroll
        for (int d = 1; d < 8; d <<= 1) {
            int n = __shfl_up_sync(0x000000ffu, s, d);
            if ((int)threadIdx.x >= d) s += n;
        }
        warp_sums[threadIdx.x] = s;
    }
    __syncthreads();
    int base = (w > 0) ? warp_sums[w - 1] : 0;
    if (i < NN) d_off[i] = base + incl - v;
    if (threadIdx.x == SCAN_B - 1) d_bsum[blockIdx.x] = base + incl;
}

// ---- scan step 2: exclusive scan of 391 block sums (single block) ----
__global__ void k_scan2() {
    __shared__ int sm[512];
    int t = threadIdx.x;
    int v = (t < NBLK) ? d_bsum[t] : 0;
    sm[t] = v;
    __syncthreads();
    for (int d = 1; d < 512; d <<= 1) {
        int add = (t >= d) ? sm[t - d] : 0;
        __syncthreads();
        sm[t] += add;
        __syncthreads();
    }
    if (t < NBLK) d_bsum[t] = sm[t] - v;
}

// ---- scan step 3: add block offsets; init cursors ----
__global__ void k_scan3() {
    int i = blockIdx.x * blockDim.x + threadIdx.x;
    if (i < NN) {
        int o = d_off[i] + d_bsum[i / SCAN_B];
        d_off[i] = o;
        d_cur[i] = o;
    }
}

// ---- fill CSR buckets ----
__global__ void k_fill(const void* __restrict__ ei) {
    int e = blockIdx.x * blockDim.x + threadIdx.x;
    if (e < NE) {
        int src = load_idx(ei, e);
        int dst = load_idx(ei, (long long)NE + e);
        int pos = atomicAdd(&d_cur[dst], 1);
        d_csr[pos] = src;
    }
}

// ---- dinv, g1 = dinv*(x@W1). 256 threads = 4 nodes x 64 cols ----
__global__ void k_node1(const float* __restrict__ x, const float* __restrict__ W1) {
    __shared__ float sW[192];
    int tid = threadIdx.x;
    if (tid < 192) sW[tid] = W1[tid];
    __syncthreads();
    int node = blockIdx.x * 4 + (tid >> 6);
    int c = tid & 63;
    float x0 = x[node * 3], x1 = x[node * 3 + 1], x2 = x[node * 3 + 2];
    float h = fmaf(x0, sW[c], fmaf(x1, sW[64 + c], x2 * sW[128 + c]));
    float di = rsqrtf((float)d_indeg[node] + 1.0f);   // +1 self loop
    if (c == 0) d_dinv[node] = di;
    d_g1[(size_t)node * 64 + c] = di * h;
}

// ---- aggregation layer 1: warp per node, float2 per lane ----
__global__ void k_agg64(const float* __restrict__ b1) {
    int gw = (blockIdx.x * blockDim.x + threadIdx.x) >> 5;
    int lane = threadIdx.x & 31;
    if (gw >= NN) return;
    int base = d_off[gw];
    int cnt = d_indeg[gw];
    const float2* G = (const float2*)d_g1;
    float2 acc = G[(size_t)gw * 32 + lane];   // self-loop term
    for (int j = 0; j < cnt; j += 32) {
        int idx = j + lane;
        int s = (idx < cnt) ? d_csr[base + idx] : 0;
        int lim = min(32, cnt - j);
#pragma unroll 4
        for (int k = 0; k < lim; k++) {
            int sk = __shfl_sync(0xffffffffu, s, k);
            float2 v = G[(size_t)sk * 32 + lane];
            acc.x += v.x;
            acc.y += v.y;
        }
    }
    float di = d_dinv[gw];
    float o0 = fmaxf(fmaf(di, acc.x, b1[2 * lane]), 0.0f);
    float o1 = fmaxf(fmaf(di, acc.y, b1[2 * lane + 1]), 0.0f);
    ((float2*)d_h1)[(size_t)gw * 32 + lane] = make_float2(o0, o1);
}

// ---- g2 = dinv*(h1@W2). 8 warps, one node per warp; W2 in shared ----
__global__ void k_node2(const float* __restrict__ W2) {
    __shared__ float sW[64 * 128];
    __shared__ float sh[8][64];
    int tid = threadIdx.x;
    for (int i = tid; i < 8192; i += 256) sW[i] = W2[i];
    int warp = tid >> 5, lane = tid & 31;
    int node = blockIdx.x * 8 + warp;
    sh[warp][lane]      = d_h1[(size_t)node * 64 + lane];
    sh[warp][lane + 32] = d_h1[(size_t)node * 64 + 32 + lane];
    __syncthreads();
    float o0 = 0.f, o1 = 0.f, o2 = 0.f, o3 = 0.f;
#pragma unroll
    for (int k = 0; k < 64; k++) {
        float hk = sh[warp][k];
        const float* w = sW + k * 128 + lane;
        o0 = fmaf(hk, w[0],  o0);
        o1 = fmaf(hk, w[32], o1);
        o2 = fmaf(hk, w[64], o2);
        o3 = fmaf(hk, w[96], o3);
    }
    float di = d_dinv[node];
    size_t b = (size_t)node * 128 + lane;
    d_g2[b]      = di * o0;
    d_g2[b + 32] = di * o1;
    d_g2[b + 64] = di * o2;
    d_g2[b + 96] = di * o3;
}

// ---- aggregation layer 2: warp per node, float4 per lane ----
__global__ void k_agg128() {
    int gw = (blockIdx.x * blockDim.x + threadIdx.x) >> 5;
    int lane = threadIdx.x & 31;
    if (gw >= NN) return;
    int base = d_off[gw];
    int cnt = d_indeg[gw];
    const float4* G = (const float4*)d_g2;
    float4 acc = G[(size_t)gw * 32 + lane];   // self-loop term
    for (int j = 0; j < cnt; j += 32) {
        int idx = j + lane;
        int s = (idx < cnt) ? d_csr[base + idx] : 0;
        int lim = min(32, cnt - j);
#pragma unroll 4
        for (int k = 0; k < lim; k++) {
            int sk = __shfl_sync(0xffffffffu, s, k);
            float4 v = G[(size_t)sk * 32 + lane];
            acc.x += v.x;
            acc.y += v.y;
            acc.z += v.z;
            acc.w += v.w;
        }
    }
    float di = d_dinv[gw];
    acc.x *= di; acc.y *= di; acc.z *= di; acc.w *= di;
    ((float4*)d_h2)[(size_t)gw * 32 + lane] = acc;
}

// ---- per-graph node counts ----
__global__ void k_cnt(const void* __restrict__ batch) {
    int i = blockIdx.x * blockDim.x + threadIdx.x;
    if (i < NN) {
        int g = load_idx(batch, i);
        atomicAdd(&d_cnt[g], 1.0f);
    }
}

// ---- pooling sum over sorted batch: 32 nodes/block, flush on change ----
__global__ void k_pool(const void* __restrict__ batch, float* __restrict__ out) {
    int c = threadIdx.x;            // 0..127
    int n0 = blockIdx.x * 32;
    int cur = load_idx(batch, n0);
    float s = 0.0f;
    for (int j = 0; j < 32; j++) {
        int i = n0 + j;
        int g = load_idx(batch, i);
        if (g != cur) {
            atomicAdd(&out[cur * 128 + c], s);
            s = 0.0f;
            cur = g;
        }
        s += d_h2[(size_t)i * 128 + c];
    }
    atomicAdd(&out[cur * 128 + c], s);
}

// ---- divide by counts, add b2 ----
__global__ void k_final(float* __restrict__ out, const float* __restrict__ b2) {
    int i = blockIdx.x * blockDim.x + threadIdx.x;
    if (i < NG * NG) {
        int g = i >> 7, c = i & 127;
        out[i] = out[i] / fmaxf(d_cnt[g], 1.0f) + b2[c];
    }
}

extern "C" void kernel_launch(void* const* d_in, const int* in_sizes, int n_in,
                              void* d_out, int out_size) {
    const float* x     = (const float*)d_in[0];
    const void*  ei    = d_in[1];
    const void*  batch = d_in[2];
    const float* W1    = (const float*)d_in[3];
    const float* b1    = (const float*)d_in[4];
    const float* W2    = (const float*)d_in[5];
    const float* b2    = (const float*)d_in[6];
    float* out = (float*)d_out;

    k_probe<<<1, 32>>>(ei);
    k_zero<<<(NN + 255) / 256, 256>>>(out);
    k_count<<<(NE + 255) / 256, 256>>>(ei);
    k_scan1<<<NBLK, SCAN_B>>>();
    k_scan2<<<1, 512>>>();
    k_scan3<<<(NN + 255) / 256, 256>>>();
    k_fill<<<(NE + 255) / 256, 256>>>(ei);
    k_node1<<<NN / 4, 256>>>(x, W1);
    k_agg64<<<(NN * 32 + 255) / 256, 256>>>(b1);
    k_node2<<<NN / 8, 256>>>(W2);
    k_agg128<<<(NN * 32 + 255) / 256, 256>>>();
    k_cnt<<<(NN + 255) / 256, 256>>>(batch);
    k_pool<<<NN / 32, 128>>>(batch, out);
    k_final<<<(NG * NG + 255) / 256, 256>>>(out, b2);
}